// round 8
// baseline (speedup 1.0000x reference)
#include <cuda_runtime.h>
#include <cuda_fp16.h>
#include <math.h>

#define NN 50000
#define EE 800000
#define ETOT (NN + EE)
#define DEGCAP 96

typedef unsigned long long ull;

__device__ __half g_H16[NN * 128];   // fp16 messages (gather operand)
__device__ float  g_B[NN * 128];     // fp32 layer activations (GEMM input)
__device__ float  g_asrc[NN * 4];
__device__ float  g_adst[NN * 4];
__device__ int    g_counts[NN];
__device__ int    g_rowptr[NN + 1];
__device__ int    g_cursor[NN];
__device__ int    g_col[ETOT];
__device__ ull    g_tile[256];       // decoupled lookback: (value<<2)|status

// ---------------- packed f32x2 helpers ----------------

__device__ __forceinline__ ull pack2(float x) {
    ull r;
    asm("mov.b64 %0, {%1, %1};" : "=l"(r) : "f"(x));
    return r;
}
__device__ __forceinline__ void ffma2(ull& d, ull a, ull b) {
    asm("fma.rn.f32x2 %0, %1, %2, %0;" : "+l"(d) : "l"(a), "l"(b));
}
__device__ __forceinline__ float2 unpack2(ull v) {
    float2 f;
    asm("mov.b64 {%0, %1}, %2;" : "=f"(f.x), "=f"(f.y) : "l"(v));
    return f;
}

// ---------------- CSR build ----------------

__global__ void count_kernel(const int* __restrict__ ei, int E, int etot) {
    int i = blockIdx.x * blockDim.x + threadIdx.x;
    if (i >= etot) return;
    int dst = (i < E) ? ei[E + i] : (i - E);
    atomicAdd(&g_counts[dst], 1);
}

__device__ __forceinline__ int block_excl_scan(int v, int tid) {
    __shared__ int ws[8];
    int lane = tid & 31, wid = tid >> 5;
    int x = v;
    #pragma unroll
    for (int o = 1; o < 32; o <<= 1) {
        int t = __shfl_up_sync(0xffffffffu, x, o);
        if (lane >= o) x += t;
    }
    if (lane == 31) ws[wid] = x;
    __syncthreads();
    if (wid == 0) {
        int w = (lane < 8) ? ws[lane] : 0;
        #pragma unroll
        for (int o = 1; o < 8; o <<= 1) {
            int t = __shfl_up_sync(0xffffffffu, w, o);
            if (lane >= o) w += t;
        }
        if (lane < 8) ws[lane] = w;
    }
    __syncthreads();
    return x - v + (wid ? ws[wid - 1] : 0);
}

// single-pass scan with decoupled lookback; writes rowptr + cursor
__global__ void scan_kernel(int etot) {
    int tid = threadIdx.x;
    int b = blockIdx.x;
    int i = b * 256 + tid;
    int v = (i < NN) ? g_counts[i] : 0;
    int excl = block_excl_scan(v, tid);

    __shared__ int sm_total;
    __shared__ int sm_run;
    if (tid == 255) sm_total = excl + v;
    __syncthreads();
    int total = sm_total;

    if (tid < 32) {
        int lane = tid;
        // publish own aggregate (block 0 publishes inclusive prefix directly)
        if (lane == 0) {
            ull word = ((ull)(unsigned)total << 2) | (b == 0 ? 2ULL : 1ULL);
            atomicExch(&g_tile[b], word);
        }
        int running = 0;
        if (b > 0) {
            int p = b - 1;
            while (true) {
                int idx = p - lane;
                int st = 0, val = 0;
                if (idx >= 0) {
                    ull t;
                    do { t = *(volatile ull*)&g_tile[idx]; } while ((t & 3ULL) == 0ULL);
                    st = (int)(t & 3ULL);
                    val = (int)(t >> 2);
                }
                unsigned pmask = __ballot_sync(0xffffffffu, idx >= 0 && st == 2);
                if (pmask) {
                    int firstp = __ffs(pmask) - 1;  // nearest predecessor w/ prefix
                    if (lane > firstp) val = 0;
                    #pragma unroll
                    for (int o = 16; o > 0; o >>= 1) val += __shfl_xor_sync(0xffffffffu, val, o);
                    running += val;
                    break;
                } else {
                    if (idx < 0) val = 0;
                    #pragma unroll
                    for (int o = 16; o > 0; o >>= 1) val += __shfl_xor_sync(0xffffffffu, val, o);
                    running += val;
                    p -= 32;
                }
            }
            if (lane == 0) {
                ull word = ((ull)(unsigned)(running + total) << 2) | 2ULL;
                atomicExch(&g_tile[b], word);
            }
        }
        if (lane == 0) sm_run = running;
    }
    __syncthreads();
    int base = sm_run;
    if (i < NN) { g_rowptr[i] = base + excl; g_cursor[i] = base + excl; }
    if (i == 0) g_rowptr[NN] = etot;
}

__global__ void fill_kernel(const int* __restrict__ ei, int E, int etot) {
    int i = blockIdx.x * blockDim.x + threadIdx.x;
    if (i >= etot) return;
    int s, d;
    if (i < E) { s = ei[i]; d = ei[E + i]; }
    else       { s = i - E; d = i - E; }
    int p = atomicAdd(&g_cursor[d], 1);
    g_col[p] = s;
}

// ---------------- Fast 128x128 linear (layers 0/1), fp16 message output ----------------

__global__ void lin128_kernel(const float* __restrict__ X, const float* __restrict__ W,
                              const float* __restrict__ a_s, const float* __restrict__ a_d,
                              __half* __restrict__ H16, float* __restrict__ asrc,
                              float* __restrict__ adst, int nrows) {
    extern __shared__ float sm[];
    float* Ws = sm;              // [128][128]
    float* Xt = sm + 128 * 128;  // [128][66] transposed
    int tid = threadIdx.x;
    int row0 = blockIdx.x * 64;

    {
        const float4* Wg = (const float4*)W;
        float4* Wsh = (float4*)Ws;
        for (int i = tid; i < 128 * 32; i += 256) Wsh[i] = Wg[i];
    }
    for (int i = tid; i < 64 * 128; i += 256) {
        int m = i >> 7, k = i & 127;
        float v = (row0 + m < nrows) ? X[(row0 + m) * 128 + k] : 0.f;
        Xt[k * 66 + m] = v;
    }
    __syncthreads();

    int tn = tid & 31, tm = tid >> 5;
    int n0 = tn * 4, m0 = tm * 8;

    ull acc[4][4];
    #pragma unroll
    for (int p = 0; p < 4; p++)
        #pragma unroll
        for (int j = 0; j < 4; j++) acc[p][j] = 0ULL;

    const float* wp = Ws + n0;
    const float* xp = Xt + m0;
    #pragma unroll 4
    for (int k = 0; k < 128; k++) {
        float4 bv = *(const float4*)(wp + k * 128);
        ull b0 = pack2(bv.x), b1 = pack2(bv.y), b2 = pack2(bv.z), b3 = pack2(bv.w);
        const ull* ap = (const ull*)(xp + k * 66);
        ull a0 = ap[0], a1 = ap[1], a2 = ap[2], a3 = ap[3];
        ffma2(acc[0][0], a0, b0); ffma2(acc[0][1], a0, b1);
        ffma2(acc[0][2], a0, b2); ffma2(acc[0][3], a0, b3);
        ffma2(acc[1][0], a1, b0); ffma2(acc[1][1], a1, b1);
        ffma2(acc[1][2], a1, b2); ffma2(acc[1][3], a1, b3);
        ffma2(acc[2][0], a2, b0); ffma2(acc[2][1], a2, b1);
        ffma2(acc[2][2], a2, b2); ffma2(acc[2][3], a2, b3);
        ffma2(acc[3][0], a3, b0); ffma2(acc[3][1], a3, b1);
        ffma2(acc[3][2], a3, b2); ffma2(acc[3][3], a3, b3);
    }

    float va0 = a_s[n0], va1 = a_s[n0 + 1], va2 = a_s[n0 + 2], va3 = a_s[n0 + 3];
    float vd0 = a_d[n0], vd1 = a_d[n0 + 1], vd2 = a_d[n0 + 2], vd3 = a_d[n0 + 3];
    int head = tn >> 3;

    #pragma unroll
    for (int p = 0; p < 4; p++) {
        float2 f0 = unpack2(acc[p][0]), f1 = unpack2(acc[p][1]);
        float2 f2 = unpack2(acc[p][2]), f3 = unpack2(acc[p][3]);
        #pragma unroll
        for (int h = 0; h < 2; h++) {
            int row = row0 + m0 + 2 * p + h;
            float v0 = h ? f0.y : f0.x;
            float v1 = h ? f1.y : f1.x;
            float v2 = h ? f2.y : f2.x;
            float v3 = h ? f3.y : f3.x;
            bool valid = (row < nrows);
            if (valid) {
                __half2 p0 = __floats2half2_rn(v0, v1);
                __half2 p1 = __floats2half2_rn(v2, v3);
                uint2 u;
                u.x = *(unsigned*)&p0;
                u.y = *(unsigned*)&p1;
                *(uint2*)(H16 + row * 128 + n0) = u;
            }
            float ss = v0 * va0 + v1 * va1 + v2 * va2 + v3 * va3;
            float sd = v0 * vd0 + v1 * vd1 + v2 * vd2 + v3 * vd3;
            #pragma unroll
            for (int o = 1; o < 8; o <<= 1) {
                ss += __shfl_xor_sync(0xffffffffu, ss, o);
                sd += __shfl_xor_sync(0xffffffffu, sd, o);
            }
            if (valid && (tn & 7) == 0) {
                asrc[row * 4 + head] = ss;
                adst[row * 4 + head] = sd;
            }
        }
    }
}

// ---------------- Linear layer 2 (K=128, COUT=40), fp16 output ----------------

__global__ void lin40_kernel(const float* __restrict__ X, const float* __restrict__ W,
                             const float* __restrict__ a_s, const float* __restrict__ a_d,
                             __half* __restrict__ H16, float* __restrict__ asrc,
                             float* __restrict__ adst, int nrows) {
    extern __shared__ float sm[];
    float* Ws = sm;                 // [128][40]
    float* Xt = Ws + 128 * 40;      // [128][66]
    float* red_s = Xt + 128 * 66;   // [64]
    float* red_d = red_s + 64;      // [64]
    int tid = threadIdx.x;
    int row0 = blockIdx.x * 64;

    for (int i = tid; i < 128 * 40; i += 320) Ws[i] = W[i];
    for (int i = tid; i < 64 * 128; i += 320) {
        int m = i >> 7, k = i & 127;
        float v = (row0 + m < nrows) ? X[(row0 + m) * 128 + k] : 0.f;
        Xt[k * 66 + m] = v;
    }
    if (tid < 64) { red_s[tid] = 0.f; red_d[tid] = 0.f; }
    __syncthreads();

    int tm = tid & 7, tn = tid >> 3;
    int m0 = tm * 8;

    ull acc[4];
    #pragma unroll
    for (int j = 0; j < 4; j++) acc[j] = 0ULL;

    #pragma unroll 4
    for (int k = 0; k < 128; k++) {
        ull bw = pack2(Ws[k * 40 + tn]);
        const ull* ap = (const ull*)(Xt + k * 66 + m0);
        ffma2(acc[0], ap[0], bw);
        ffma2(acc[1], ap[1], bw);
        ffma2(acc[2], ap[2], bw);
        ffma2(acc[3], ap[3], bw);
    }

    float va = a_s[tn], vd = a_d[tn];
    #pragma unroll
    for (int p = 0; p < 4; p++) {
        float2 f = unpack2(acc[p]);
        #pragma unroll
        for (int h = 0; h < 2; h++) {
            int row = row0 + m0 + 2 * p + h;
            float v = h ? f.y : f.x;
            if (row < nrows) H16[row * 40 + tn] = __float2half_rn(v);
            float ss = v * va, sd = v * vd;
            ss += __shfl_xor_sync(0xffffffffu, ss, 8);
            ss += __shfl_xor_sync(0xffffffffu, ss, 16);
            sd += __shfl_xor_sync(0xffffffffu, sd, 8);
            sd += __shfl_xor_sync(0xffffffffu, sd, 16);
            if ((tid & 31) < 8) {
                atomicAdd(&red_s[m0 + 2 * p + h], ss);
                atomicAdd(&red_d[m0 + 2 * p + h], sd);
            }
        }
    }
    __syncthreads();
    if (tid < 64) {
        int row = row0 + tid;
        if (row < nrows) {
            asrc[row * 4] = red_s[tid];
            adst[row * 4] = red_d[tid];
        }
    }
}

// ---------------- Aggregation layers 0/1: warp per node, smem-cached logits ----------------

__global__ void agg_kernel(const __half* __restrict__ H16, const float* __restrict__ asrc,
                           const float* __restrict__ adst, const float* __restrict__ bias,
                           float* __restrict__ Hout) {
    __shared__ int   colbuf[8][DEGCAP];
    __shared__ float lgbuf[8][DEGCAP][4];
    int node = (blockIdx.x * blockDim.x + threadIdx.x) >> 5;
    if (node >= NN) return;
    int lane = threadIdx.x & 31;
    int wip = (threadIdx.x >> 5) & 7;
    int head = lane >> 3;
    int s = g_rowptr[node], e = g_rowptr[node + 1];
    int deg = e - s;
    float4 ad4 = ((const float4*)adst)[node];
    bool fast = (deg <= DEGCAP);

    // phase 1: per-head max; cache (col, logits) in smem on fast path
    float m0 = -INFINITY, m1 = -INFINITY, m2 = -INFINITY, m3 = -INFINITY;
    for (int i = lane; i < deg; i += 32) {
        int src = g_col[s + i];
        float4 av = ((const float4*)asrc)[src];
        float l0 = av.x + ad4.x; l0 = fmaxf(l0, 0.2f * l0);
        float l1 = av.y + ad4.y; l1 = fmaxf(l1, 0.2f * l1);
        float l2 = av.z + ad4.z; l2 = fmaxf(l2, 0.2f * l2);
        float l3 = av.w + ad4.w; l3 = fmaxf(l3, 0.2f * l3);
        if (fast) {
            colbuf[wip][i] = src;
            *(float4*)&lgbuf[wip][i][0] = make_float4(l0, l1, l2, l3);
        }
        m0 = fmaxf(m0, l0); m1 = fmaxf(m1, l1);
        m2 = fmaxf(m2, l2); m3 = fmaxf(m3, l3);
    }
    #pragma unroll
    for (int o = 16; o > 0; o >>= 1) {
        m0 = fmaxf(m0, __shfl_xor_sync(0xffffffffu, m0, o));
        m1 = fmaxf(m1, __shfl_xor_sync(0xffffffffu, m1, o));
        m2 = fmaxf(m2, __shfl_xor_sync(0xffffffffu, m2, o));
        m3 = fmaxf(m3, __shfl_xor_sync(0xffffffffu, m3, o));
    }
    float mh = (head == 0) ? m0 : (head == 1) ? m1 : (head == 2) ? m2 : m3;
    float adh = (head == 0) ? ad4.x : (head == 1) ? ad4.y : (head == 2) ? ad4.z : ad4.w;
    __syncwarp();

    // phase 2
    float ssum = 0.f, a0 = 0.f, a1 = 0.f, a2 = 0.f, a3 = 0.f;
    if (fast) {
        #pragma unroll 4
        for (int i = 0; i < deg; i++) {
            int src = colbuf[wip][i];
            float lg = lgbuf[wip][i][head];
            float ce = __expf(lg - mh);
            uint2 u = ((const uint2*)(H16 + src * 128))[lane];
            float2 hlo = __half22float2(*(const __half2*)&u.x);
            float2 hhi = __half22float2(*(const __half2*)&u.y);
            ssum += ce;
            a0 = fmaf(ce, hlo.x, a0);
            a1 = fmaf(ce, hlo.y, a1);
            a2 = fmaf(ce, hhi.x, a2);
            a3 = fmaf(ce, hhi.y, a3);
        }
    } else {
        #pragma unroll 4
        for (int i = s; i < e; i++) {
            int src = g_col[i];
            float lg = asrc[src * 4 + head] + adh;
            lg = fmaxf(lg, 0.2f * lg);
            float ce = __expf(lg - mh);
            uint2 u = ((const uint2*)(H16 + src * 128))[lane];
            float2 hlo = __half22float2(*(const __half2*)&u.x);
            float2 hhi = __half22float2(*(const __half2*)&u.y);
            ssum += ce;
            a0 = fmaf(ce, hlo.x, a0);
            a1 = fmaf(ce, hlo.y, a1);
            a2 = fmaf(ce, hhi.x, a2);
            a3 = fmaf(ce, hhi.y, a3);
        }
    }
    float inv = 1.f / (ssum + 1e-16f);
    float4 b4 = *(const float4*)(bias + lane * 4);
    float o0 = a0 * inv + b4.x;
    float o1 = a1 * inv + b4.y;
    float o2 = a2 * inv + b4.z;
    float o3 = a3 * inv + b4.w;
    o0 = o0 > 0.f ? o0 : expm1f(o0);
    o1 = o1 > 0.f ? o1 : expm1f(o1);
    o2 = o2 > 0.f ? o2 : expm1f(o2);
    o3 = o3 > 0.f ? o3 : expm1f(o3);
    *(float4*)(Hout + node * 128 + lane * 4) = make_float4(o0, o1, o2, o3);
}

// ---------------- Aggregation layer 2: warp per node, smem-cached logits ----------------

__global__ void agg2_kernel(const __half* __restrict__ H16, const float* __restrict__ asrc,
                            const float* __restrict__ adst, const float* __restrict__ bias,
                            float* __restrict__ out) {
    __shared__ int   colbuf[8][DEGCAP];
    __shared__ float lgbuf[8][DEGCAP];
    int node = (blockIdx.x * blockDim.x + threadIdx.x) >> 5;
    if (node >= NN) return;
    int lane = threadIdx.x & 31;
    int wip = (threadIdx.x >> 5) & 7;
    int s = g_rowptr[node], e = g_rowptr[node + 1];
    int deg = e - s;
    float ad = adst[node * 4];
    bool fast = (deg <= DEGCAP);

    float mh = -INFINITY;
    for (int i = lane; i < deg; i += 32) {
        int src = g_col[s + i];
        float lg = asrc[src * 4] + ad;
        lg = fmaxf(lg, 0.2f * lg);
        if (fast) { colbuf[wip][i] = src; lgbuf[wip][i] = lg; }
        mh = fmaxf(mh, lg);
    }
    #pragma unroll
    for (int o = 16; o > 0; o >>= 1) mh = fmaxf(mh, __shfl_xor_sync(0xffffffffu, mh, o));
    __syncwarp();

    bool active = (lane < 20);
    float ssum = 0.f, aLo = 0.f, aHi = 0.f;
    if (fast) {
        #pragma unroll 4
        for (int i = 0; i < deg; i++) {
            int src = colbuf[wip][i];
            float ce = __expf(lgbuf[wip][i] - mh);
            ssum += ce;
            if (active) {
                unsigned u = *(const unsigned*)(H16 + src * 40 + lane * 2);
                float2 hv = __half22float2(*(const __half2*)&u);
                aLo = fmaf(ce, hv.x, aLo);
                aHi = fmaf(ce, hv.y, aHi);
            }
        }
    } else {
        #pragma unroll 4
        for (int i = s; i < e; i++) {
            int src = g_col[i];
            float lg = asrc[src * 4] + ad;
            lg = fmaxf(lg, 0.2f * lg);
            float ce = __expf(lg - mh);
            ssum += ce;
            if (active) {
                unsigned u = *(const unsigned*)(H16 + src * 40 + lane * 2);
                float2 hv = __half22float2(*(const __half2*)&u);
                aLo = fmaf(ce, hv.x, aLo);
                aHi = fmaf(ce, hv.y, aHi);
            }
        }
    }
    float inv = 1.f / (ssum + 1e-16f);
    float vLo = active ? (aLo * inv + bias[lane * 2])     : -INFINITY;
    float vHi = active ? (aHi * inv + bias[lane * 2 + 1]) : -INFINITY;
    float mx = fmaxf(vLo, vHi);
    #pragma unroll
    for (int o = 16; o > 0; o >>= 1) mx = fmaxf(mx, __shfl_xor_sync(0xffffffffu, mx, o));
    float se = active ? (__expf(vLo - mx) + __expf(vHi - mx)) : 0.f;
    #pragma unroll
    for (int o = 16; o > 0; o >>= 1) se += __shfl_xor_sync(0xffffffffu, se, o);
    float lse = mx + logf(se);
    if (active) {
        float2 r = make_float2(vLo - lse, vHi - lse);
        *(float2*)(out + node * 40 + lane * 2) = r;
    }
}

// ---------------- host ----------------

extern "C" void kernel_launch(void* const* d_in, const int* in_sizes, int n_in,
                              void* d_out, int out_size) {
    const float* x   = (const float*)d_in[0];
    const int*   ei  = (const int*)d_in[1];
    const float* W0  = (const float*)d_in[2];
    const float* as0 = (const float*)d_in[3];
    const float* ad0 = (const float*)d_in[4];
    const float* b0  = (const float*)d_in[5];
    const float* W1  = (const float*)d_in[6];
    const float* as1 = (const float*)d_in[7];
    const float* ad1 = (const float*)d_in[8];
    const float* b1  = (const float*)d_in[9];
    const float* W2  = (const float*)d_in[10];
    const float* as2 = (const float*)d_in[11];
    const float* ad2 = (const float*)d_in[12];
    const float* b2  = (const float*)d_in[13];
    float* out = (float*)d_out;

    int E = in_sizes[1] / 2;
    int etot = E + NN;

    __half* H16;
    float *B, *asrc, *adst;
    int* counts;
    ull* tiles;
    cudaGetSymbolAddress((void**)&H16, g_H16);
    cudaGetSymbolAddress((void**)&B, g_B);
    cudaGetSymbolAddress((void**)&asrc, g_asrc);
    cudaGetSymbolAddress((void**)&adst, g_adst);
    cudaGetSymbolAddress((void**)&counts, g_counts);
    cudaGetSymbolAddress((void**)&tiles, g_tile);

    const int NB = (NN + 255) / 256;  // 196

    cudaMemsetAsync(counts, 0, NN * sizeof(int));
    cudaMemsetAsync(tiles, 0, 256 * sizeof(ull));
    count_kernel<<<(etot + 511) / 512, 512>>>(ei, E, etot);   // kernel 1
    scan_kernel<<<NB, 256>>>(etot);                           // kernel 2
    fill_kernel<<<(etot + 511) / 512, 512>>>(ei, E, etot);    // kernel 3

    const int smem_lin128 = (128 * 128 + 128 * 66) * 4;         // 99328
    const int smem_lin40  = (128 * 40 + 128 * 66 + 128) * 4;    // 54784
    cudaFuncSetAttribute(lin128_kernel, cudaFuncAttributeMaxDynamicSharedMemorySize, smem_lin128);
    cudaFuncSetAttribute(lin40_kernel, cudaFuncAttributeMaxDynamicSharedMemorySize, smem_lin40);

    int lin_grid = (NN + 63) / 64;            // 782
    int agg_grid = (NN * 32 + 255) / 256;     // warp per node

    // layer 0 (lin128 is kernel 4 -> ncu capture target)
    lin128_kernel<<<lin_grid, 256, smem_lin128>>>(x, W0, as0, ad0, H16, asrc, adst, NN);
    agg_kernel<<<agg_grid, 256>>>(H16, asrc, adst, b0, B);
    // layer 1
    lin128_kernel<<<lin_grid, 256, smem_lin128>>>(B, W1, as1, ad1, H16, asrc, adst, NN);
    agg_kernel<<<agg_grid, 256>>>(H16, asrc, adst, b1, B);
    // layer 2
    lin40_kernel<<<lin_grid, 320, smem_lin40>>>(B, W2, as2, ad2, H16, asrc, adst, NN);
    agg2_kernel<<<agg_grid, 256>>>(H16, asrc, adst, b2, out);

    (void)n_in; (void)out_size;
}

// round 10
// speedup vs baseline: 1.1386x; 1.1386x over previous
#include <cuda_runtime.h>
#include <cuda_fp16.h>
#include <math.h>
#include <cstdint>

#define NN 50000
#define EE 800000
#define ETOT (NN + EE)
#define DEGCAP 96

typedef unsigned long long ull;

__device__ __half g_H16[NN * 128];   // fp16 messages (gather operand)
__device__ float  g_B[NN * 128];     // fp32 layer activations (GEMM input)
__device__ float  g_asrc[NN * 4];
__device__ float  g_adst[NN * 4];
__device__ int    g_counts[NN];
__device__ int    g_rowptr[NN + 1];
__device__ int    g_cursor[NN];
__device__ int    g_col[ETOT];
__device__ ull    g_tile[256];       // decoupled lookback: (value<<2)|status
__device__ __half g_Wh[2][16384];    // fp16-hi of W0, W1
__device__ __half g_Wl[2][16384];    // fp16-lo of W0, W1

// ---------------- packed f32x2 helpers (for lin40) ----------------

__device__ __forceinline__ ull pack2(float x) {
    ull r;
    asm("mov.b64 %0, {%1, %1};" : "=l"(r) : "f"(x));
    return r;
}
__device__ __forceinline__ void ffma2(ull& d, ull a, ull b) {
    asm("fma.rn.f32x2 %0, %1, %2, %0;" : "+l"(d) : "l"(a), "l"(b));
}
__device__ __forceinline__ float2 unpack2(ull v) {
    float2 f;
    asm("mov.b64 {%0, %1}, %2;" : "=f"(f.x), "=f"(f.y) : "l"(v));
    return f;
}

// ---------------- MMA helpers ----------------

__device__ __forceinline__ unsigned smem_u32(const void* p) {
    unsigned r;
    asm("{ .reg .u64 t; cvta.to.shared.u64 t, %1; cvt.u32.u64 %0, t; }"
        : "=r"(r) : "l"(p));
    return r;
}
__device__ __forceinline__ uint4 ldsm_x4(unsigned addr) {
    uint4 r;
    asm volatile("ldmatrix.sync.aligned.m8n8.x4.shared.b16 {%0,%1,%2,%3}, [%4];"
        : "=r"(r.x), "=r"(r.y), "=r"(r.z), "=r"(r.w) : "r"(addr));
    return r;
}
__device__ __forceinline__ uint2 ldsm_x2t(unsigned addr) {
    uint2 r;
    asm volatile("ldmatrix.sync.aligned.m8n8.x2.trans.shared.b16 {%0,%1}, [%2];"
        : "=r"(r.x), "=r"(r.y) : "r"(addr));
    return r;
}
__device__ __forceinline__ void mma16816(float* c, const uint4& a, const uint2& b) {
    asm volatile("mma.sync.aligned.m16n8k16.row.col.f32.f16.f16.f32 "
        "{%0,%1,%2,%3}, {%4,%5,%6,%7}, {%8,%9}, {%0,%1,%2,%3};"
        : "+f"(c[0]), "+f"(c[1]), "+f"(c[2]), "+f"(c[3])
        : "r"(a.x), "r"(a.y), "r"(a.z), "r"(a.w), "r"(b.x), "r"(b.y));
}

// hi/lo split: hi = top 11 mantissa bits (exactly fp16-representable), lo = residual
__device__ __forceinline__ void split2(float x, float y, unsigned& hi, unsigned& lo) {
    float hx = __uint_as_float(__float_as_uint(x) & 0xFFFFE000u);
    float hy = __uint_as_float(__float_as_uint(y) & 0xFFFFE000u);
    __half2 h = __floats2half2_rn(hx, hy);
    __half2 l = __floats2half2_rn(x - hx, y - hy);
    hi = *(unsigned*)&h;
    lo = *(unsigned*)&l;
}

// ---------------- W split (once per launch) ----------------

__global__ void wsplit_kernel(const float* __restrict__ W0, const float* __restrict__ W1) {
    int i = blockIdx.x * blockDim.x + threadIdx.x;   // 0..32767
    int which = i >> 14;
    int j = i & 16383;
    float v = which ? W1[j] : W0[j];
    float hf = __uint_as_float(__float_as_uint(v) & 0xFFFFE000u);
    g_Wh[which][j] = __float2half_rn(hf);
    g_Wl[which][j] = __float2half_rn(v - hf);
}

// ---------------- CSR build ----------------

__global__ void count_kernel(const int* __restrict__ ei, int E, int etot) {
    int i = blockIdx.x * blockDim.x + threadIdx.x;
    if (i >= etot) return;
    int dst = (i < E) ? ei[E + i] : (i - E);
    atomicAdd(&g_counts[dst], 1);
}

__device__ __forceinline__ int block_excl_scan(int v, int tid) {
    __shared__ int ws[8];
    int lane = tid & 31, wid = tid >> 5;
    int x = v;
    #pragma unroll
    for (int o = 1; o < 32; o <<= 1) {
        int t = __shfl_up_sync(0xffffffffu, x, o);
        if (lane >= o) x += t;
    }
    if (lane == 31) ws[wid] = x;
    __syncthreads();
    if (wid == 0) {
        int w = (lane < 8) ? ws[lane] : 0;
        #pragma unroll
        for (int o = 1; o < 8; o <<= 1) {
            int t = __shfl_up_sync(0xffffffffu, w, o);
            if (lane >= o) w += t;
        }
        if (lane < 8) ws[lane] = w;
    }
    __syncthreads();
    return x - v + (wid ? ws[wid - 1] : 0);
}

__global__ void scan_kernel(int etot) {
    int tid = threadIdx.x;
    int b = blockIdx.x;
    int i = b * 256 + tid;
    int v = (i < NN) ? g_counts[i] : 0;
    int excl = block_excl_scan(v, tid);

    __shared__ int sm_total;
    __shared__ int sm_run;
    if (tid == 255) sm_total = excl + v;
    __syncthreads();
    int total = sm_total;

    if (tid < 32) {
        int lane = tid;
        if (lane == 0) {
            ull word = ((ull)(unsigned)total << 2) | (b == 0 ? 2ULL : 1ULL);
            atomicExch(&g_tile[b], word);
        }
        int running = 0;
        if (b > 0) {
            int p = b - 1;
            while (true) {
                int idx = p - lane;
                int st = 0, val = 0;
                if (idx >= 0) {
                    ull t;
                    do { t = *(volatile ull*)&g_tile[idx]; } while ((t & 3ULL) == 0ULL);
                    st = (int)(t & 3ULL);
                    val = (int)(t >> 2);
                }
                unsigned pmask = __ballot_sync(0xffffffffu, idx >= 0 && st == 2);
                if (pmask) {
                    int firstp = __ffs(pmask) - 1;
                    if (lane > firstp) val = 0;
                    #pragma unroll
                    for (int o = 16; o > 0; o >>= 1) val += __shfl_xor_sync(0xffffffffu, val, o);
                    running += val;
                    break;
                } else {
                    if (idx < 0) val = 0;
                    #pragma unroll
                    for (int o = 16; o > 0; o >>= 1) val += __shfl_xor_sync(0xffffffffu, val, o);
                    running += val;
                    p -= 32;
                }
            }
            if (lane == 0) {
                ull word = ((ull)(unsigned)(running + total) << 2) | 2ULL;
                atomicExch(&g_tile[b], word);
            }
        }
        if (lane == 0) sm_run = running;
    }
    __syncthreads();
    int base = sm_run;
    if (i < NN) { g_rowptr[i] = base + excl; g_cursor[i] = base + excl; }
    if (i == 0) g_rowptr[NN] = etot;
}

__global__ void fill_kernel(const int* __restrict__ ei, int E, int etot) {
    int i = blockIdx.x * blockDim.x + threadIdx.x;
    if (i >= etot) return;
    int s, d;
    if (i < E) { s = ei[i]; d = ei[E + i]; }
    else       { s = i - E; d = i - E; }
    int p = atomicAdd(&g_cursor[d], 1);
    g_col[p] = s;
}

// ---------------- Tensor-core 128x128 linear (layers 0/1) ----------------
// C = Ah@Wh + Al@Wh + Ah@Wl (fp32-grade). Block: 256 thr, tile M=64, N=128, K=128.
// Warp grid: 4 (M) x 2 (N); warp = 16 rows x 64 cols (8 n-tiles of m16n8k16).

__global__ void lin128_mma_kernel(const float* __restrict__ X,
                                  const __half* __restrict__ Whg, const __half* __restrict__ Wlg,
                                  const float* __restrict__ a_s, const float* __restrict__ a_d,
                                  __half* __restrict__ H16, float* __restrict__ asrc,
                                  float* __restrict__ adst, int nrows) {
    extern __shared__ char smraw[];
    __half* Ah  = (__half*)smraw;          // [64][136]
    __half* Al  = Ah + 64 * 136;
    __half* Whs = Al + 64 * 136;           // [128][136]
    __half* Wls = Whs + 128 * 136;
    float* as_sm = (float*)(Wls + 128 * 136);  // [128]
    float* ad_sm = as_sm + 128;                // [128]
    float* red_s = ad_sm + 128;                // [64*4]
    float* red_d = red_s + 256;                // [64*4]

    int tid = threadIdx.x;
    int row0 = blockIdx.x * 64;

    // W copy (pre-split fp16 in global): 2048 uint4 per array
    {
        const uint4* WhG = (const uint4*)Whg;
        const uint4* WlG = (const uint4*)Wlg;
        for (int i = tid; i < 2048; i += 256) {
            int k = i >> 4, c8 = i & 15;
            *(uint4*)(Whs + k * 136 + c8 * 8) = WhG[i];
            *(uint4*)(Wls + k * 136 + c8 * 8) = WlG[i];
        }
    }
    // X tile load + split: 64 rows x 32 float4
    for (int i = tid; i < 2048; i += 256) {
        int r = i >> 5, c4 = i & 31;
        int row = row0 + r;
        float4 v = (row < nrows) ? ((const float4*)X)[row * 32 + c4]
                                 : make_float4(0.f, 0.f, 0.f, 0.f);
        unsigned h01, l01, h23, l23;
        split2(v.x, v.y, h01, l01);
        split2(v.z, v.w, h23, l23);
        uint2 uh; uh.x = h01; uh.y = h23;
        uint2 ul; ul.x = l01; ul.y = l23;
        *(uint2*)(Ah + r * 136 + c4 * 4) = uh;
        *(uint2*)(Al + r * 136 + c4 * 4) = ul;
    }
    if (tid < 128) { as_sm[tid] = a_s[tid]; ad_sm[tid] = a_d[tid]; }
    if (tid < 256) { red_s[tid] = 0.f; red_d[tid] = 0.f; }
    __syncthreads();

    int lane = tid & 31, wid = tid >> 5;
    int warp_m = wid & 3, warp_n = wid >> 2;

    unsigned sAh = smem_u32(Ah);
    unsigned sAl = smem_u32(Al);
    unsigned sWh = smem_u32(Whs);
    unsigned sWl = smem_u32(Wls);

    unsigned aRow = warp_m * 16 + (lane & 15);
    unsigned aCol = (lane >> 4) * 8;
    unsigned ahBase = sAh + aRow * 272 + aCol * 2;
    unsigned alBase = sAl + aRow * 272 + aCol * 2;
    unsigned bRow = lane & 15;

    float acc[8][4];
    #pragma unroll
    for (int nt = 0; nt < 8; nt++)
        #pragma unroll
        for (int j = 0; j < 4; j++) acc[nt][j] = 0.f;

    #pragma unroll 2
    for (int kk = 0; kk < 8; kk++) {
        int k0 = kk * 16;
        uint4 afh = ldsm_x4(ahBase + k0 * 2);
        uint4 afl = ldsm_x4(alBase + k0 * 2);
        unsigned whRow = sWh + (k0 + bRow) * 272 + warp_n * 128;  // + nt*16 bytes
        unsigned wlRow = sWl + (k0 + bRow) * 272 + warp_n * 128;
        #pragma unroll
        for (int nt = 0; nt < 8; nt++) {
            uint2 bh = ldsm_x2t(whRow + nt * 16);
            uint2 bl = ldsm_x2t(wlRow + nt * 16);
            mma16816(acc[nt], afh, bh);
            mma16816(acc[nt], afl, bh);
            mma16816(acc[nt], afh, bl);
        }
    }

    // epilogue: write H16, accumulate per-head logits
    int g = lane >> 2, t = lane & 3;
    int r1 = warp_m * 16 + g, r2 = r1 + 8;
    int row1 = row0 + r1, row2 = row0 + r2;
    float ps1[2] = {0.f, 0.f}, pd1[2] = {0.f, 0.f};
    float ps2[2] = {0.f, 0.f}, pd2[2] = {0.f, 0.f};
    #pragma unroll
    for (int nt = 0; nt < 8; nt++) {
        int col = warp_n * 64 + nt * 8 + t * 2;
        int hg = nt >> 2;  // head group within warp's 64 cols
        float c0 = acc[nt][0], c1 = acc[nt][1], c2 = acc[nt][2], c3 = acc[nt][3];
        if (row1 < nrows) {
            __half2 p = __floats2half2_rn(c0, c1);
            *(__half2*)(H16 + row1 * 128 + col) = p;
        }
        if (row2 < nrows) {
            __half2 p = __floats2half2_rn(c2, c3);
            *(__half2*)(H16 + row2 * 128 + col) = p;
        }
        float2 av = *(float2*)&as_sm[col];
        float2 dv = *(float2*)&ad_sm[col];
        ps1[hg] += c0 * av.x + c1 * av.y;
        pd1[hg] += c0 * dv.x + c1 * dv.y;
        ps2[hg] += c2 * av.x + c3 * av.y;
        pd2[hg] += c2 * dv.x + c3 * dv.y;
    }
    #pragma unroll
    for (int hg = 0; hg < 2; hg++) {
        ps1[hg] += __shfl_xor_sync(0xffffffffu, ps1[hg], 1);
        ps1[hg] += __shfl_xor_sync(0xffffffffu, ps1[hg], 2);
        pd1[hg] += __shfl_xor_sync(0xffffffffu, pd1[hg], 1);
        pd1[hg] += __shfl_xor_sync(0xffffffffu, pd1[hg], 2);
        ps2[hg] += __shfl_xor_sync(0xffffffffu, ps2[hg], 1);
        ps2[hg] += __shfl_xor_sync(0xffffffffu, ps2[hg], 2);
        pd2[hg] += __shfl_xor_sync(0xffffffffu, pd2[hg], 1);
        pd2[hg] += __shfl_xor_sync(0xffffffffu, pd2[hg], 2);
    }
    if (t == 0) {
        #pragma unroll
        for (int hg = 0; hg < 2; hg++) {
            int h = warp_n * 2 + hg;
            atomicAdd(&red_s[r1 * 4 + h], ps1[hg]);
            atomicAdd(&red_d[r1 * 4 + h], pd1[hg]);
            atomicAdd(&red_s[r2 * 4 + h], ps2[hg]);
            atomicAdd(&red_d[r2 * 4 + h], pd2[hg]);
        }
    }
    __syncthreads();
    {
        int r = tid >> 2;
        int row = row0 + r;
        if (row < nrows) {
            asrc[row * 4 + (tid & 3)] = red_s[tid];
            adst[row * 4 + (tid & 3)] = red_d[tid];
        }
    }
}

// ---------------- Linear layer 2 (K=128, COUT=40), fp16 output ----------------

__global__ void lin40_kernel(const float* __restrict__ X, const float* __restrict__ W,
                             const float* __restrict__ a_s, const float* __restrict__ a_d,
                             __half* __restrict__ H16, float* __restrict__ asrc,
                             float* __restrict__ adst, int nrows) {
    extern __shared__ float sm[];
    float* Ws = sm;                 // [128][40]
    float* Xt = Ws + 128 * 40;      // [128][66]
    float* red_s = Xt + 128 * 66;   // [64]
    float* red_d = red_s + 64;      // [64]
    int tid = threadIdx.x;
    int row0 = blockIdx.x * 64;

    for (int i = tid; i < 128 * 40; i += 320) Ws[i] = W[i];
    for (int i = tid; i < 64 * 128; i += 320) {
        int m = i >> 7, k = i & 127;
        float v = (row0 + m < nrows) ? X[(row0 + m) * 128 + k] : 0.f;
        Xt[k * 66 + m] = v;
    }
    if (tid < 64) { red_s[tid] = 0.f; red_d[tid] = 0.f; }
    __syncthreads();

    int tm = tid & 7, tn = tid >> 3;
    int m0 = tm * 8;

    ull acc[4];
    #pragma unroll
    for (int j = 0; j < 4; j++) acc[j] = 0ULL;

    #pragma unroll 4
    for (int k = 0; k < 128; k++) {
        ull bw = pack2(Ws[k * 40 + tn]);
        const ull* ap = (const ull*)(Xt + k * 66 + m0);
        ffma2(acc[0], ap[0], bw);
        ffma2(acc[1], ap[1], bw);
        ffma2(acc[2], ap[2], bw);
        ffma2(acc[3], ap[3], bw);
    }

    float va = a_s[tn], vd = a_d[tn];
    #pragma unroll
    for (int p = 0; p < 4; p++) {
        float2 f = unpack2(acc[p]);
        #pragma unroll
        for (int h = 0; h < 2; h++) {
            int row = row0 + m0 + 2 * p + h;
            float v = h ? f.y : f.x;
            if (row < nrows) H16[row * 40 + tn] = __float2half_rn(v);
            float ss = v * va, sd = v * vd;
            ss += __shfl_xor_sync(0xffffffffu, ss, 8);
            ss += __shfl_xor_sync(0xffffffffu, ss, 16);
            sd += __shfl_xor_sync(0xffffffffu, sd, 8);
            sd += __shfl_xor_sync(0xffffffffu, sd, 16);
            if ((tid & 31) < 8) {
                atomicAdd(&red_s[m0 + 2 * p + h], ss);
                atomicAdd(&red_d[m0 + 2 * p + h], sd);
            }
        }
    }
    __syncthreads();
    if (tid < 64) {
        int row = row0 + tid;
        if (row < nrows) {
            asrc[row * 4] = red_s[tid];
            adst[row * 4] = red_d[tid];
        }
    }
}

// ---------------- Aggregation layers 0/1: warp per node, smem-cached logits ----------------

__global__ void agg_kernel(const __half* __restrict__ H16, const float* __restrict__ asrc,
                           const float* __restrict__ adst, const float* __restrict__ bias,
                           float* __restrict__ Hout) {
    __shared__ int   colbuf[8][DEGCAP];
    __shared__ float lgbuf[8][DEGCAP][4];
    int node = (blockIdx.x * blockDim.x + threadIdx.x) >> 5;
    if (node >= NN) return;
    int lane = threadIdx.x & 31;
    int wip = (threadIdx.x >> 5) & 7;
    int head = lane >> 3;
    int s = g_rowptr[node], e = g_rowptr[node + 1];
    int deg = e - s;
    float4 ad4 = ((const float4*)adst)[node];
    bool fast = (deg <= DEGCAP);

    float m0 = -INFINITY, m1 = -INFINITY, m2 = -INFINITY, m3 = -INFINITY;
    for (int i = lane; i < deg; i += 32) {
        int src = g_col[s + i];
        float4 av = ((const float4*)asrc)[src];
        float l0 = av.x + ad4.x; l0 = fmaxf(l0, 0.2f * l0);
        float l1 = av.y + ad4.y; l1 = fmaxf(l1, 0.2f * l1);
        float l2 = av.z + ad4.z; l2 = fmaxf(l2, 0.2f * l2);
        float l3 = av.w + ad4.w; l3 = fmaxf(l3, 0.2f * l3);
        if (fast) {
            colbuf[wip][i] = src;
            *(float4*)&lgbuf[wip][i][0] = make_float4(l0, l1, l2, l3);
        }
        m0 = fmaxf(m0, l0); m1 = fmaxf(m1, l1);
        m2 = fmaxf(m2, l2); m3 = fmaxf(m3, l3);
    }
    #pragma unroll
    for (int o = 16; o > 0; o >>= 1) {
        m0 = fmaxf(m0, __shfl_xor_sync(0xffffffffu, m0, o));
        m1 = fmaxf(m1, __shfl_xor_sync(0xffffffffu, m1, o));
        m2 = fmaxf(m2, __shfl_xor_sync(0xffffffffu, m2, o));
        m3 = fmaxf(m3, __shfl_xor_sync(0xffffffffu, m3, o));
    }
    float mh = (head == 0) ? m0 : (head == 1) ? m1 : (head == 2) ? m2 : m3;
    float adh = (head == 0) ? ad4.x : (head == 1) ? ad4.y : (head == 2) ? ad4.z : ad4.w;
    __syncwarp();

    float ssum = 0.f, a0 = 0.f, a1 = 0.f, a2 = 0.f, a3 = 0.f;
    if (fast) {
        #pragma unroll 4
        for (int i = 0; i < deg; i++) {
            int src = colbuf[wip][i];
            float lg = lgbuf[wip][i][head];
            float ce = __expf(lg - mh);
            uint2 u = ((const uint2*)(H16 + src * 128))[lane];
            float2 hlo = __half22float2(*(const __half2*)&u.x);
            float2 hhi = __half22float2(*(const __half2*)&u.y);
            ssum += ce;
            a0 = fmaf(ce, hlo.x, a0);
            a1 = fmaf(ce, hlo.y, a1);
            a2 = fmaf(ce, hhi.x, a2);
            a3 = fmaf(ce, hhi.y, a3);
        }
    } else {
        #pragma unroll 4
        for (int i = s; i < e; i++) {
            int src = g_col[i];
            float lg = asrc[src * 4 + head] + adh;
            lg = fmaxf(lg, 0.2f * lg);
            float ce = __expf(lg - mh);
            uint2 u = ((const uint2*)(H16 + src * 128))[lane];
            float2 hlo = __half22float2(*(const __half2*)&u.x);
            float2 hhi = __half22float2(*(const __half2*)&u.y);
            ssum += ce;
            a0 = fmaf(ce, hlo.x, a0);
            a1 = fmaf(ce, hlo.y, a1);
            a2 = fmaf(ce, hhi.x, a2);
            a3 = fmaf(ce, hhi.y, a3);
        }
    }
    float inv = 1.f / (ssum + 1e-16f);
    float4 b4 = *(const float4*)(bias + lane * 4);
    float o0 = a0 * inv + b4.x;
    float o1 = a1 * inv + b4.y;
    float o2 = a2 * inv + b4.z;
    float o3 = a3 * inv + b4.w;
    o0 = o0 > 0.f ? o0 : expm1f(o0);
    o1 = o1 > 0.f ? o1 : expm1f(o1);
    o2 = o2 > 0.f ? o2 : expm1f(o2);
    o3 = o3 > 0.f ? o3 : expm1f(o3);
    *(float4*)(Hout + node * 128 + lane * 4) = make_float4(o0, o1, o2, o3);
}

// ---------------- Aggregation layer 2: warp per node, smem-cached logits ----------------

__global__ void agg2_kernel(const __half* __restrict__ H16, const float* __restrict__ asrc,
                            const float* __restrict__ adst, const float* __restrict__ bias,
                            float* __restrict__ out) {
    __shared__ int   colbuf[8][DEGCAP];
    __shared__ float lgbuf[8][DEGCAP];
    int node = (blockIdx.x * blockDim.x + threadIdx.x) >> 5;
    if (node >= NN) return;
    int lane = threadIdx.x & 31;
    int wip = (threadIdx.x >> 5) & 7;
    int s = g_rowptr[node], e = g_rowptr[node + 1];
    int deg = e - s;
    float ad = adst[node * 4];
    bool fast = (deg <= DEGCAP);

    float mh = -INFINITY;
    for (int i = lane; i < deg; i += 32) {
        int src = g_col[s + i];
        float lg = asrc[src * 4] + ad;
        lg = fmaxf(lg, 0.2f * lg);
        if (fast) { colbuf[wip][i] = src; lgbuf[wip][i] = lg; }
        mh = fmaxf(mh, lg);
    }
    #pragma unroll
    for (int o = 16; o > 0; o >>= 1) mh = fmaxf(mh, __shfl_xor_sync(0xffffffffu, mh, o));
    __syncwarp();

    bool active = (lane < 20);
    float ssum = 0.f, aLo = 0.f, aHi = 0.f;
    if (fast) {
        #pragma unroll 4
        for (int i = 0; i < deg; i++) {
            int src = colbuf[wip][i];
            float ce = __expf(lgbuf[wip][i] - mh);
            ssum += ce;
            if (active) {
                unsigned u = *(const unsigned*)(H16 + src * 40 + lane * 2);
                float2 hv = __half22float2(*(const __half2*)&u);
                aLo = fmaf(ce, hv.x, aLo);
                aHi = fmaf(ce, hv.y, aHi);
            }
        }
    } else {
        #pragma unroll 4
        for (int i = s; i < e; i++) {
            int src = g_col[i];
            float lg = asrc[src * 4] + ad;
            lg = fmaxf(lg, 0.2f * lg);
            float ce = __expf(lg - mh);
            ssum += ce;
            if (active) {
                unsigned u = *(const unsigned*)(H16 + src * 40 + lane * 2);
                float2 hv = __half22float2(*(const __half2*)&u);
                aLo = fmaf(ce, hv.x, aLo);
                aHi = fmaf(ce, hv.y, aHi);
            }
        }
    }
    float inv = 1.f / (ssum + 1e-16f);
    float vLo = active ? (aLo * inv + bias[lane * 2])     : -INFINITY;
    float vHi = active ? (aHi * inv + bias[lane * 2 + 1]) : -INFINITY;
    float mx = fmaxf(vLo, vHi);
    #pragma unroll
    for (int o = 16; o > 0; o >>= 1) mx = fmaxf(mx, __shfl_xor_sync(0xffffffffu, mx, o));
    float se = active ? (__expf(vLo - mx) + __expf(vHi - mx)) : 0.f;
    #pragma unroll
    for (int o = 16; o > 0; o >>= 1) se += __shfl_xor_sync(0xffffffffu, se, o);
    float lse = mx + logf(se);
    if (active) {
        float2 r = make_float2(vLo - lse, vHi - lse);
        *(float2*)(out + node * 40 + lane * 2) = r;
    }
}

// ---------------- host ----------------

extern "C" void kernel_launch(void* const* d_in, const int* in_sizes, int n_in,
                              void* d_out, int out_size) {
    const float* x   = (const float*)d_in[0];
    const int*   ei  = (const int*)d_in[1];
    const float* W0  = (const float*)d_in[2];
    const float* as0 = (const float*)d_in[3];
    const float* ad0 = (const float*)d_in[4];
    const float* b0  = (const float*)d_in[5];
    const float* W1  = (const float*)d_in[6];
    const float* as1 = (const float*)d_in[7];
    const float* ad1 = (const float*)d_in[8];
    const float* b1  = (const float*)d_in[9];
    const float* W2  = (const float*)d_in[10];
    const float* as2 = (const float*)d_in[11];
    const float* ad2 = (const float*)d_in[12];
    const float* b2  = (const float*)d_in[13];
    float* out = (float*)d_out;

    int E = in_sizes[1] / 2;
    int etot = E + NN;

    __half* H16;
    float *B, *asrc, *adst;
    int* counts;
    ull* tiles;
    __half *Wh, *Wl;
    cudaGetSymbolAddress((void**)&H16, g_H16);
    cudaGetSymbolAddress((void**)&B, g_B);
    cudaGetSymbolAddress((void**)&asrc, g_asrc);
    cudaGetSymbolAddress((void**)&adst, g_adst);
    cudaGetSymbolAddress((void**)&counts, g_counts);
    cudaGetSymbolAddress((void**)&tiles, g_tile);
    cudaGetSymbolAddress((void**)&Wh, g_Wh);
    cudaGetSymbolAddress((void**)&Wl, g_Wl);

    const int NB = (NN + 255) / 256;  // 196

    cudaMemsetAsync(counts, 0, NN * sizeof(int));
    cudaMemsetAsync(tiles, 0, 256 * sizeof(ull));
    wsplit_kernel<<<128, 256>>>(W0, W1);                       // k1
    count_kernel<<<(etot + 511) / 512, 512>>>(ei, E, etot);    // k2
    scan_kernel<<<NB, 256>>>(etot);                            // k3

    const int smem_mma = 107520;
    const int smem_lin40 = (128 * 40 + 128 * 66 + 128) * 4;    // 54784
    cudaFuncSetAttribute(lin128_mma_kernel, cudaFuncAttributeMaxDynamicSharedMemorySize, smem_mma);
    cudaFuncSetAttribute(lin40_kernel, cudaFuncAttributeMaxDynamicSharedMemorySize, smem_lin40);

    int lin_grid = (NN + 63) / 64;            // 782
    int agg_grid = (NN * 32 + 255) / 256;     // warp per node

    // layer 0 GEMM before fill (independent of CSR); k4 = ncu capture target
    lin128_mma_kernel<<<lin_grid, 256, smem_mma>>>(x, Wh, Wl, as0, ad0, H16, asrc, adst, NN);
    fill_kernel<<<(etot + 511) / 512, 512>>>(ei, E, etot);     // k5
    agg_kernel<<<agg_grid, 256>>>(H16, asrc, adst, b0, B);
    // layer 1
    lin128_mma_kernel<<<lin_grid, 256, smem_mma>>>(B, Wh + 16384, Wl + 16384, as1, ad1, H16, asrc, adst, NN);
    agg_kernel<<<agg_grid, 256>>>(H16, asrc, adst, b1, B);
    // layer 2
    lin40_kernel<<<lin_grid, 320, smem_lin40>>>(B, W2, as2, ad2, H16, asrc, adst, NN);
    agg2_kernel<<<agg_grid, 256>>>(H16, asrc, adst, b2, out);

    (void)n_in; (void)out_size;
}

// round 11
// speedup vs baseline: 1.1922x; 1.0470x over previous
#include <cuda_runtime.h>
#include <cuda_fp16.h>
#include <math.h>
#include <cstdint>

#define NN 50000
#define EE 800000
#define ETOT (NN + EE)
#define DEGCAP 96

typedef unsigned long long ull;

__device__ __half g_H16[NN * 128];   // fp16 messages (gather operand)
__device__ __half g_A16[NN * 128];   // fp16 activations (next-layer GEMM input)
__device__ float  g_asrc[NN * 4];
__device__ float  g_adst[NN * 4];
__device__ int    g_counts[NN];
__device__ int    g_rowptr[NN + 1];
__device__ int    g_cursor[NN];
__device__ int    g_col[ETOT];
__device__ ull    g_tile[256];       // decoupled lookback: (value<<2)|status
__device__ __half g_Wh[2][16384];    // fp16-hi of W0, W1
__device__ __half g_Wl[2][16384];    // fp16-lo of W0, W1

// ---------------- MMA helpers ----------------

__device__ __forceinline__ unsigned smem_u32(const void* p) {
    unsigned r;
    asm("{ .reg .u64 t; cvta.to.shared.u64 t, %1; cvt.u32.u64 %0, t; }"
        : "=r"(r) : "l"(p));
    return r;
}
__device__ __forceinline__ uint4 ldsm_x4(unsigned addr) {
    uint4 r;
    asm volatile("ldmatrix.sync.aligned.m8n8.x4.shared.b16 {%0,%1,%2,%3}, [%4];"
        : "=r"(r.x), "=r"(r.y), "=r"(r.z), "=r"(r.w) : "r"(addr));
    return r;
}
__device__ __forceinline__ uint4 ldsm_x4t(unsigned addr) {
    uint4 r;
    asm volatile("ldmatrix.sync.aligned.m8n8.x4.trans.shared.b16 {%0,%1,%2,%3}, [%4];"
        : "=r"(r.x), "=r"(r.y), "=r"(r.z), "=r"(r.w) : "r"(addr));
    return r;
}
__device__ __forceinline__ void mma16816(float* c, const uint4& a, unsigned b0, unsigned b1) {
    asm volatile("mma.sync.aligned.m16n8k16.row.col.f32.f16.f16.f32 "
        "{%0,%1,%2,%3}, {%4,%5,%6,%7}, {%8,%9}, {%0,%1,%2,%3};"
        : "+f"(c[0]), "+f"(c[1]), "+f"(c[2]), "+f"(c[3])
        : "r"(a.x), "r"(a.y), "r"(a.z), "r"(a.w), "r"(b0), "r"(b1));
}

// hi/lo split: hi = top 11 mantissa bits (exactly fp16-representable), lo = residual
__device__ __forceinline__ void split2(float x, float y, unsigned& hi, unsigned& lo) {
    float hx = __uint_as_float(__float_as_uint(x) & 0xFFFFE000u);
    float hy = __uint_as_float(__float_as_uint(y) & 0xFFFFE000u);
    __half2 h = __floats2half2_rn(hx, hy);
    __half2 l = __floats2half2_rn(x - hx, y - hy);
    hi = *(unsigned*)&h;
    lo = *(unsigned*)&l;
}

// ---------------- W split (once per launch) ----------------

__global__ void wsplit_kernel(const float* __restrict__ W0, const float* __restrict__ W1) {
    int i = blockIdx.x * blockDim.x + threadIdx.x;   // 0..32767
    int which = i >> 14;
    int j = i & 16383;
    float v = which ? W1[j] : W0[j];
    float hf = __uint_as_float(__float_as_uint(v) & 0xFFFFE000u);
    g_Wh[which][j] = __float2half_rn(hf);
    g_Wl[which][j] = __float2half_rn(v - hf);
}

// ---------------- CSR build ----------------

__global__ void count_kernel(const int* __restrict__ ei, int E, int etot) {
    int i = blockIdx.x * blockDim.x + threadIdx.x;
    if (i >= etot) return;
    int dst = (i < E) ? ei[E + i] : (i - E);
    atomicAdd(&g_counts[dst], 1);
}

__device__ __forceinline__ int block_excl_scan(int v, int tid) {
    __shared__ int ws[8];
    int lane = tid & 31, wid = tid >> 5;
    int x = v;
    #pragma unroll
    for (int o = 1; o < 32; o <<= 1) {
        int t = __shfl_up_sync(0xffffffffu, x, o);
        if (lane >= o) x += t;
    }
    if (lane == 31) ws[wid] = x;
    __syncthreads();
    if (wid == 0) {
        int w = (lane < 8) ? ws[lane] : 0;
        #pragma unroll
        for (int o = 1; o < 8; o <<= 1) {
            int t = __shfl_up_sync(0xffffffffu, w, o);
            if (lane >= o) w += t;
        }
        if (lane < 8) ws[lane] = w;
    }
    __syncthreads();
    return x - v + (wid ? ws[wid - 1] : 0);
}

__global__ void scan_kernel(int etot) {
    int tid = threadIdx.x;
    int b = blockIdx.x;
    int i = b * 256 + tid;
    int v = (i < NN) ? g_counts[i] : 0;
    int excl = block_excl_scan(v, tid);

    __shared__ int sm_total;
    __shared__ int sm_run;
    if (tid == 255) sm_total = excl + v;
    __syncthreads();
    int total = sm_total;

    if (tid < 32) {
        int lane = tid;
        if (lane == 0) {
            ull word = ((ull)(unsigned)total << 2) | (b == 0 ? 2ULL : 1ULL);
            atomicExch(&g_tile[b], word);
        }
        int running = 0;
        if (b > 0) {
            int p = b - 1;
            while (true) {
                int idx = p - lane;
                int st = 0, val = 0;
                if (idx >= 0) {
                    ull t;
                    do { t = *(volatile ull*)&g_tile[idx]; } while ((t & 3ULL) == 0ULL);
                    st = (int)(t & 3ULL);
                    val = (int)(t >> 2);
                }
                unsigned pmask = __ballot_sync(0xffffffffu, idx >= 0 && st == 2);
                if (pmask) {
                    int firstp = __ffs(pmask) - 1;
                    if (lane > firstp) val = 0;
                    #pragma unroll
                    for (int o = 16; o > 0; o >>= 1) val += __shfl_xor_sync(0xffffffffu, val, o);
                    running += val;
                    break;
                } else {
                    if (idx < 0) val = 0;
                    #pragma unroll
                    for (int o = 16; o > 0; o >>= 1) val += __shfl_xor_sync(0xffffffffu, val, o);
                    running += val;
                    p -= 32;
                }
            }
            if (lane == 0) {
                ull word = ((ull)(unsigned)(running + total) << 2) | 2ULL;
                atomicExch(&g_tile[b], word);
            }
        }
        if (lane == 0) sm_run = running;
    }
    __syncthreads();
    int base = sm_run;
    if (i < NN) { g_rowptr[i] = base + excl; g_cursor[i] = base + excl; }
    if (i == 0) g_rowptr[NN] = etot;
}

__global__ void fill_kernel(const int* __restrict__ ei, int E, int etot) {
    int i = blockIdx.x * blockDim.x + threadIdx.x;
    if (i >= etot) return;
    int s, d;
    if (i < E) { s = ei[i]; d = ei[E + i]; }
    else       { s = i - E; d = i - E; }
    int p = atomicAdd(&g_cursor[d], 1);
    g_col[p] = s;
}

// ---------------- shared epilogue for lin128 MMA kernels ----------------

__device__ __forceinline__ void lin128_epilogue(
    float acc[8][4], const float* as_sm, const float* ad_sm,
    float* red_s, float* red_d,
    __half* H16, float* asrc, float* adst,
    int row0, int nrows, int lane, int warp_m, int warp_n, int tid
) {
    int g = lane >> 2, t = lane & 3;
    int r1 = warp_m * 16 + g, r2 = r1 + 8;
    int row1 = row0 + r1, row2 = row0 + r2;
    float ps1[2] = {0.f, 0.f}, pd1[2] = {0.f, 0.f};
    float ps2[2] = {0.f, 0.f}, pd2[2] = {0.f, 0.f};
    #pragma unroll
    for (int nt = 0; nt < 8; nt++) {
        int col = warp_n * 64 + nt * 8 + t * 2;
        int hg = nt >> 2;
        float c0 = acc[nt][0], c1 = acc[nt][1], c2 = acc[nt][2], c3 = acc[nt][3];
        if (row1 < nrows) {
            __half2 p = __floats2half2_rn(c0, c1);
            *(__half2*)(H16 + row1 * 128 + col) = p;
        }
        if (row2 < nrows) {
            __half2 p = __floats2half2_rn(c2, c3);
            *(__half2*)(H16 + row2 * 128 + col) = p;
        }
        float2 av = *(float2*)&as_sm[col];
        float2 dv = *(float2*)&ad_sm[col];
        ps1[hg] += c0 * av.x + c1 * av.y;
        pd1[hg] += c0 * dv.x + c1 * dv.y;
        ps2[hg] += c2 * av.x + c3 * av.y;
        pd2[hg] += c2 * dv.x + c3 * dv.y;
    }
    #pragma unroll
    for (int hg = 0; hg < 2; hg++) {
        ps1[hg] += __shfl_xor_sync(0xffffffffu, ps1[hg], 1);
        ps1[hg] += __shfl_xor_sync(0xffffffffu, ps1[hg], 2);
        pd1[hg] += __shfl_xor_sync(0xffffffffu, pd1[hg], 1);
        pd1[hg] += __shfl_xor_sync(0xffffffffu, pd1[hg], 2);
        ps2[hg] += __shfl_xor_sync(0xffffffffu, ps2[hg], 1);
        ps2[hg] += __shfl_xor_sync(0xffffffffu, ps2[hg], 2);
        pd2[hg] += __shfl_xor_sync(0xffffffffu, pd2[hg], 1);
        pd2[hg] += __shfl_xor_sync(0xffffffffu, pd2[hg], 2);
    }
    if (t == 0) {
        #pragma unroll
        for (int hg = 0; hg < 2; hg++) {
            int h = warp_n * 2 + hg;
            atomicAdd(&red_s[r1 * 4 + h], ps1[hg]);
            atomicAdd(&red_d[r1 * 4 + h], pd1[hg]);
            atomicAdd(&red_s[r2 * 4 + h], ps2[hg]);
            atomicAdd(&red_d[r2 * 4 + h], pd2[hg]);
        }
    }
    __syncthreads();
    {
        int r = tid >> 2;
        int row = row0 + r;
        if (row < nrows) {
            asrc[row * 4 + (tid & 3)] = red_s[tid];
            adst[row * 4 + (tid & 3)] = red_d[tid];
        }
    }
}

// ---------------- Layer 0: fp32 input, 3-term MMA (Ah@Wh + Al@Wh + Ah@Wl) ----------------

__global__ void lin128_mma3_kernel(const float* __restrict__ X,
                                   const __half* __restrict__ Whg, const __half* __restrict__ Wlg,
                                   const float* __restrict__ a_s, const float* __restrict__ a_d,
                                   __half* __restrict__ H16, float* __restrict__ asrc,
                                   float* __restrict__ adst, int nrows) {
    extern __shared__ char smraw[];
    __half* Ah  = (__half*)smraw;              // [64][136]
    __half* Al  = Ah + 64 * 136;
    __half* Whs = Al + 64 * 136;               // [128][136]
    __half* Wls = Whs + 128 * 136;
    float* as_sm = (float*)(Wls + 128 * 136);
    float* ad_sm = as_sm + 128;
    float* red_s = ad_sm + 128;
    float* red_d = red_s + 256;

    int tid = threadIdx.x;
    int row0 = blockIdx.x * 64;

    {
        const uint4* WhG = (const uint4*)Whg;
        const uint4* WlG = (const uint4*)Wlg;
        for (int i = tid; i < 2048; i += 256) {
            int k = i >> 4, c8 = i & 15;
            *(uint4*)(Whs + k * 136 + c8 * 8) = WhG[i];
            *(uint4*)(Wls + k * 136 + c8 * 8) = WlG[i];
        }
    }
    for (int i = tid; i < 2048; i += 256) {
        int r = i >> 5, c4 = i & 31;
        int row = row0 + r;
        float4 v = (row < nrows) ? ((const float4*)X)[row * 32 + c4]
                                 : make_float4(0.f, 0.f, 0.f, 0.f);
        unsigned h01, l01, h23, l23;
        split2(v.x, v.y, h01, l01);
        split2(v.z, v.w, h23, l23);
        uint2 uh; uh.x = h01; uh.y = h23;
        uint2 ul; ul.x = l01; ul.y = l23;
        *(uint2*)(Ah + r * 136 + c4 * 4) = uh;
        *(uint2*)(Al + r * 136 + c4 * 4) = ul;
    }
    if (tid < 128) { as_sm[tid] = a_s[tid]; ad_sm[tid] = a_d[tid]; }
    if (tid < 256) { red_s[tid] = 0.f; red_d[tid] = 0.f; }
    __syncthreads();

    int lane = tid & 31, wid = tid >> 5;
    int warp_m = wid & 3, warp_n = wid >> 2;

    unsigned ahBase = smem_u32(Ah) + (warp_m * 16 + (lane & 15)) * 272 + (lane >> 4) * 16;
    unsigned alBase = smem_u32(Al) + (warp_m * 16 + (lane & 15)) * 272 + (lane >> 4) * 16;
    unsigned bhBase = smem_u32(Whs) + warp_n * 128 + (lane & 15) * 272 + (lane >> 4) * 16;
    unsigned blBase = smem_u32(Wls) + warp_n * 128 + (lane & 15) * 272 + (lane >> 4) * 16;

    float acc[8][4];
    #pragma unroll
    for (int nt = 0; nt < 8; nt++)
        #pragma unroll
        for (int j = 0; j < 4; j++) acc[nt][j] = 0.f;

    #pragma unroll 2
    for (int kk = 0; kk < 8; kk++) {
        unsigned kOff = kk * 16 * 272;
        uint4 afh = ldsm_x4(ahBase + kk * 32);
        uint4 afl = ldsm_x4(alBase + kk * 32);
        #pragma unroll
        for (int ntp = 0; ntp < 4; ntp++) {
            uint4 bh = ldsm_x4t(bhBase + kOff + ntp * 32);
            uint4 bl = ldsm_x4t(blBase + kOff + ntp * 32);
            mma16816(acc[2 * ntp],     afh, bh.x, bh.y);
            mma16816(acc[2 * ntp],     afl, bh.x, bh.y);
            mma16816(acc[2 * ntp],     afh, bl.x, bl.y);
            mma16816(acc[2 * ntp + 1], afh, bh.z, bh.w);
            mma16816(acc[2 * ntp + 1], afl, bh.z, bh.w);
            mma16816(acc[2 * ntp + 1], afh, bl.z, bl.w);
        }
    }

    lin128_epilogue(acc, as_sm, ad_sm, red_s, red_d, H16, asrc, adst,
                    row0, nrows, lane, warp_m, warp_n, tid);
}

// ---------------- Layer 1: fp16 input (exact), 2-term MMA (A@Wh + A@Wl) ----------------

__global__ void lin128_mma2_kernel(const __half* __restrict__ X,
                                   const __half* __restrict__ Whg, const __half* __restrict__ Wlg,
                                   const float* __restrict__ a_s, const float* __restrict__ a_d,
                                   __half* __restrict__ H16, float* __restrict__ asrc,
                                   float* __restrict__ adst, int nrows) {
    extern __shared__ char smraw[];
    __half* Ah  = (__half*)smraw;              // [64][136]
    __half* Whs = Ah + 64 * 136;               // [128][136]
    __half* Wls = Whs + 128 * 136;
    float* as_sm = (float*)(Wls + 128 * 136);
    float* ad_sm = as_sm + 128;
    float* red_s = ad_sm + 128;
    float* red_d = red_s + 256;

    int tid = threadIdx.x;
    int row0 = blockIdx.x * 64;

    {
        const uint4* WhG = (const uint4*)Whg;
        const uint4* WlG = (const uint4*)Wlg;
        for (int i = tid; i < 2048; i += 256) {
            int k = i >> 4, c8 = i & 15;
            *(uint4*)(Whs + k * 136 + c8 * 8) = WhG[i];
            *(uint4*)(Wls + k * 136 + c8 * 8) = WlG[i];
        }
    }
    // A copy: 64 rows x 16 uint4 (fp16 already)
    for (int i = tid; i < 1024; i += 256) {
        int r = i >> 4, c8 = i & 15;
        int row = row0 + r;
        uint4 v = (row < nrows) ? *(const uint4*)(X + row * 128 + c8 * 8)
                                : make_uint4(0, 0, 0, 0);
        *(uint4*)(Ah + r * 136 + c8 * 8) = v;
    }
    if (tid < 128) { as_sm[tid] = a_s[tid]; ad_sm[tid] = a_d[tid]; }
    if (tid < 256) { red_s[tid] = 0.f; red_d[tid] = 0.f; }
    __syncthreads();

    int lane = tid & 31, wid = tid >> 5;
    int warp_m = wid & 3, warp_n = wid >> 2;

    unsigned ahBase = smem_u32(Ah) + (warp_m * 16 + (lane & 15)) * 272 + (lane >> 4) * 16;
    unsigned bhBase = smem_u32(Whs) + warp_n * 128 + (lane & 15) * 272 + (lane >> 4) * 16;
    unsigned blBase = smem_u32(Wls) + warp_n * 128 + (lane & 15) * 272 + (lane >> 4) * 16;

    float acc[8][4];
    #pragma unroll
    for (int nt = 0; nt < 8; nt++)
        #pragma unroll
        for (int j = 0; j < 4; j++) acc[nt][j] = 0.f;

    #pragma unroll 2
    for (int kk = 0; kk < 8; kk++) {
        unsigned kOff = kk * 16 * 272;
        uint4 af = ldsm_x4(ahBase + kk * 32);
        #pragma unroll
        for (int ntp = 0; ntp < 4; ntp++) {
            uint4 bh = ldsm_x4t(bhBase + kOff + ntp * 32);
            uint4 bl = ldsm_x4t(blBase + kOff + ntp * 32);
            mma16816(acc[2 * ntp],     af, bh.x, bh.y);
            mma16816(acc[2 * ntp],     af, bl.x, bl.y);
            mma16816(acc[2 * ntp + 1], af, bh.z, bh.w);
            mma16816(acc[2 * ntp + 1], af, bl.z, bl.w);
        }
    }

    lin128_epilogue(acc, as_sm, ad_sm, red_s, red_d, H16, asrc, adst,
                    row0, nrows, lane, warp_m, warp_n, tid);
}

// ---------------- Linear layer 2 (K=128, COUT=40), fp16 in/out ----------------

__global__ void lin40_kernel(const __half* __restrict__ X, const float* __restrict__ W,
                             const float* __restrict__ a_s, const float* __restrict__ a_d,
                             __half* __restrict__ H16, float* __restrict__ asrc,
                             float* __restrict__ adst, int nrows) {
    extern __shared__ float sm[];
    float* Ws = sm;                 // [128][40]
    float* Xt = Ws + 128 * 40;      // [128][66]
    float* red_s = Xt + 128 * 66;   // [64]
    float* red_d = red_s + 64;      // [64]
    int tid = threadIdx.x;
    int row0 = blockIdx.x * 64;

    typedef unsigned long long u64;
    for (int i = tid; i < 128 * 40; i += 320) Ws[i] = W[i];
    for (int i = tid; i < 64 * 128; i += 320) {
        int m = i >> 7, k = i & 127;
        float v = (row0 + m < nrows) ? __half2float(X[(row0 + m) * 128 + k]) : 0.f;
        Xt[k * 66 + m] = v;
    }
    if (tid < 64) { red_s[tid] = 0.f; red_d[tid] = 0.f; }
    __syncthreads();

    int tm = tid & 7, tn = tid >> 3;
    int m0 = tm * 8;

    u64 acc[4] = {0ULL, 0ULL, 0ULL, 0ULL};

    #pragma unroll 4
    for (int k = 0; k < 128; k++) {
        float wv = Ws[k * 40 + tn];
        u64 bw;
        asm("mov.b64 %0, {%1, %1};" : "=l"(bw) : "f"(wv));
        const u64* ap = (const u64*)(Xt + k * 66 + m0);
        asm("fma.rn.f32x2 %0, %1, %2, %0;" : "+l"(acc[0]) : "l"(ap[0]), "l"(bw));
        asm("fma.rn.f32x2 %0, %1, %2, %0;" : "+l"(acc[1]) : "l"(ap[1]), "l"(bw));
        asm("fma.rn.f32x2 %0, %1, %2, %0;" : "+l"(acc[2]) : "l"(ap[2]), "l"(bw));
        asm("fma.rn.f32x2 %0, %1, %2, %0;" : "+l"(acc[3]) : "l"(ap[3]), "l"(bw));
    }

    float va = a_s[tn], vd = a_d[tn];
    #pragma unroll
    for (int p = 0; p < 4; p++) {
        float fx, fy;
        asm("mov.b64 {%0, %1}, %2;" : "=f"(fx), "=f"(fy) : "l"(acc[p]));
        #pragma unroll
        for (int h = 0; h < 2; h++) {
            int row = row0 + m0 + 2 * p + h;
            float v = h ? fy : fx;
            if (row < nrows) H16[row * 40 + tn] = __float2half_rn(v);
            float ss = v * va, sd = v * vd;
            ss += __shfl_xor_sync(0xffffffffu, ss, 8);
            ss += __shfl_xor_sync(0xffffffffu, ss, 16);
            sd += __shfl_xor_sync(0xffffffffu, sd, 8);
            sd += __shfl_xor_sync(0xffffffffu, sd, 16);
            if ((tid & 31) < 8) {
                atomicAdd(&red_s[m0 + 2 * p + h], ss);
                atomicAdd(&red_d[m0 + 2 * p + h], sd);
            }
        }
    }
    __syncthreads();
    if (tid < 64) {
        int row = row0 + tid;
        if (row < nrows) {
            asrc[row * 4] = red_s[tid];
            adst[row * 4] = red_d[tid];
        }
    }
}

// ---------------- Aggregation layers 0/1: warp per node, fp16 in AND out ----------------

__global__ void agg_kernel(const __half* __restrict__ H16, const float* __restrict__ asrc,
                           const float* __restrict__ adst, const float* __restrict__ bias,
                           __half* __restrict__ Aout) {
    __shared__ int   colbuf[8][DEGCAP];
    __shared__ float lgbuf[8][DEGCAP][4];
    int node = (blockIdx.x * blockDim.x + threadIdx.x) >> 5;
    if (node >= NN) return;
    int lane = threadIdx.x & 31;
    int wip = (threadIdx.x >> 5) & 7;
    int head = lane >> 3;
    int s = g_rowptr[node], e = g_rowptr[node + 1];
    int deg = e - s;
    float4 ad4 = ((const float4*)adst)[node];
    bool fast = (deg <= DEGCAP);

    float m0 = -INFINITY, m1 = -INFINITY, m2 = -INFINITY, m3 = -INFINITY;
    for (int i = lane; i < deg; i += 32) {
        int src = g_col[s + i];
        float4 av = ((const float4*)asrc)[src];
        float l0 = av.x + ad4.x; l0 = fmaxf(l0, 0.2f * l0);
        float l1 = av.y + ad4.y; l1 = fmaxf(l1, 0.2f * l1);
        float l2 = av.z + ad4.z; l2 = fmaxf(l2, 0.2f * l2);
        float l3 = av.w + ad4.w; l3 = fmaxf(l3, 0.2f * l3);
        if (fast) {
            colbuf[wip][i] = src;
            *(float4*)&lgbuf[wip][i][0] = make_float4(l0, l1, l2, l3);
        }
        m0 = fmaxf(m0, l0); m1 = fmaxf(m1, l1);
        m2 = fmaxf(m2, l2); m3 = fmaxf(m3, l3);
    }
    #pragma unroll
    for (int o = 16; o > 0; o >>= 1) {
        m0 = fmaxf(m0, __shfl_xor_sync(0xffffffffu, m0, o));
        m1 = fmaxf(m1, __shfl_xor_sync(0xffffffffu, m1, o));
        m2 = fmaxf(m2, __shfl_xor_sync(0xffffffffu, m2, o));
        m3 = fmaxf(m3, __shfl_xor_sync(0xffffffffu, m3, o));
    }
    float mh = (head == 0) ? m0 : (head == 1) ? m1 : (head == 2) ? m2 : m3;
    float adh = (head == 0) ? ad4.x : (head == 1) ? ad4.y : (head == 2) ? ad4.z : ad4.w;
    __syncwarp();

    float ssum = 0.f, a0 = 0.f, a1 = 0.f, a2 = 0.f, a3 = 0.f;
    if (fast) {
        #pragma unroll 4
        for (int i = 0; i < deg; i++) {
            int src = colbuf[wip][i];
            float lg = lgbuf[wip][i][head];
            float ce = __expf(lg - mh);
            uint2 u = ((const uint2*)(H16 + src * 128))[lane];
            float2 hlo = __half22float2(*(const __half2*)&u.x);
            float2 hhi = __half22float2(*(const __half2*)&u.y);
            ssum += ce;
            a0 = fmaf(ce, hlo.x, a0);
            a1 = fmaf(ce, hlo.y, a1);
            a2 = fmaf(ce, hhi.x, a2);
            a3 = fmaf(ce, hhi.y, a3);
        }
    } else {
        #pragma unroll 4
        for (int i = s; i < e; i++) {
            int src = g_col[i];
            float lg = asrc[src * 4 + head] + adh;
            lg = fmaxf(lg, 0.2f * lg);
            float ce = __expf(lg - mh);
            uint2 u = ((const uint2*)(H16 + src * 128))[lane];
            float2 hlo = __half22float2(*(const __half2*)&u.x);
            float2 hhi = __half22float2(*(const __half2*)&u.y);
            ssum += ce;
            a0 = fmaf(ce, hlo.x, a0);
            a1 = fmaf(ce, hlo.y, a1);
            a2 = fmaf(ce, hhi.x, a2);
            a3 = fmaf(ce, hhi.y, a3);
        }
    }
    float inv = 1.f / (ssum + 1e-16f);
    float4 b4 = *(const float4*)(bias + lane * 4);
    float o0 = a0 * inv + b4.x;
    float o1 = a1 * inv + b4.y;
    float o2 = a2 * inv + b4.z;
    float o3 = a3 * inv + b4.w;
    o0 = o0 > 0.f ? o0 : expm1f(o0);
    o1 = o1 > 0.f ? o1 : expm1f(o1);
    o2 = o2 > 0.f ? o2 : expm1f(o2);
    o3 = o3 > 0.f ? o3 : expm1f(o3);
    __half2 p0 = __floats2half2_rn(o0, o1);
    __half2 p1 = __floats2half2_rn(o2, o3);
    uint2 u;
    u.x = *(unsigned*)&p0;
    u.y = *(unsigned*)&p1;
    *(uint2*)(Aout + node * 128 + lane * 4) = u;
}

// ---------------- Aggregation layer 2: warp per node, smem-cached logits ----------------

__global__ void agg2_kernel(const __half* __restrict__ H16, const float* __restrict__ asrc,
                            const float* __restrict__ adst, const float* __restrict__ bias,
                            float* __restrict__ out) {
    __shared__ int   colbuf[8][DEGCAP];
    __shared__ float lgbuf[8][DEGCAP];
    int node = (blockIdx.x * blockDim.x + threadIdx.x) >> 5;
    if (node >= NN) return;
    int lane = threadIdx.x & 31;
    int wip = (threadIdx.x >> 5) & 7;
    int s = g_rowptr[node], e = g_rowptr[node + 1];
    int deg = e - s;
    float ad = adst[node * 4];
    bool fast = (deg <= DEGCAP);

    float mh = -INFINITY;
    for (int i = lane; i < deg; i += 32) {
        int src = g_col[s + i];
        float lg = asrc[src * 4] + ad;
        lg = fmaxf(lg, 0.2f * lg);
        if (fast) { colbuf[wip][i] = src; lgbuf[wip][i] = lg; }
        mh = fmaxf(mh, lg);
    }
    #pragma unroll
    for (int o = 16; o > 0; o >>= 1) mh = fmaxf(mh, __shfl_xor_sync(0xffffffffu, mh, o));
    __syncwarp();

    bool active = (lane < 20);
    float ssum = 0.f, aLo = 0.f, aHi = 0.f;
    if (fast) {
        #pragma unroll 4
        for (int i = 0; i < deg; i++) {
            int src = colbuf[wip][i];
            float ce = __expf(lgbuf[wip][i] - mh);
            ssum += ce;
            if (active) {
                unsigned u = *(const unsigned*)(H16 + src * 40 + lane * 2);
                float2 hv = __half22float2(*(const __half2*)&u);
                aLo = fmaf(ce, hv.x, aLo);
                aHi = fmaf(ce, hv.y, aHi);
            }
        }
    } else {
        #pragma unroll 4
        for (int i = s; i < e; i++) {
            int src = g_col[i];
            float lg = asrc[src * 4] + ad;
            lg = fmaxf(lg, 0.2f * lg);
            float ce = __expf(lg - mh);
            ssum += ce;
            if (active) {
                unsigned u = *(const unsigned*)(H16 + src * 40 + lane * 2);
                float2 hv = __half22float2(*(const __half2*)&u);
                aLo = fmaf(ce, hv.x, aLo);
                aHi = fmaf(ce, hv.y, aHi);
            }
        }
    }
    float inv = 1.f / (ssum + 1e-16f);
    float vLo = active ? (aLo * inv + bias[lane * 2])     : -INFINITY;
    float vHi = active ? (aHi * inv + bias[lane * 2 + 1]) : -INFINITY;
    float mx = fmaxf(vLo, vHi);
    #pragma unroll
    for (int o = 16; o > 0; o >>= 1) mx = fmaxf(mx, __shfl_xor_sync(0xffffffffu, mx, o));
    float se = active ? (__expf(vLo - mx) + __expf(vHi - mx)) : 0.f;
    #pragma unroll
    for (int o = 16; o > 0; o >>= 1) se += __shfl_xor_sync(0xffffffffu, se, o);
    float lse = mx + logf(se);
    if (active) {
        float2 r = make_float2(vLo - lse, vHi - lse);
        *(float2*)(out + node * 40 + lane * 2) = r;
    }
}

// ---------------- host ----------------

extern "C" void kernel_launch(void* const* d_in, const int* in_sizes, int n_in,
                              void* d_out, int out_size) {
    const float* x   = (const float*)d_in[0];
    const int*   ei  = (const int*)d_in[1];
    const float* W0  = (const float*)d_in[2];
    const float* as0 = (const float*)d_in[3];
    const float* ad0 = (const float*)d_in[4];
    const float* b0  = (const float*)d_in[5];
    const float* W1  = (const float*)d_in[6];
    const float* as1 = (const float*)d_in[7];
    const float* ad1 = (const float*)d_in[8];
    const float* b1  = (const float*)d_in[9];
    const float* W2  = (const float*)d_in[10];
    const float* as2 = (const float*)d_in[11];
    const float* ad2 = (const float*)d_in[12];
    const float* b2  = (const float*)d_in[13];
    float* out = (float*)d_out;

    int E = in_sizes[1] / 2;
    int etot = E + NN;

    __half *H16, *A16;
    float *asrc, *adst;
    int* counts;
    ull* tiles;
    __half *Wh, *Wl;
    cudaGetSymbolAddress((void**)&H16, g_H16);
    cudaGetSymbolAddress((void**)&A16, g_A16);
    cudaGetSymbolAddress((void**)&asrc, g_asrc);
    cudaGetSymbolAddress((void**)&adst, g_adst);
    cudaGetSymbolAddress((void**)&counts, g_counts);
    cudaGetSymbolAddress((void**)&tiles, g_tile);
    cudaGetSymbolAddress((void**)&Wh, g_Wh);
    cudaGetSymbolAddress((void**)&Wl, g_Wl);

    const int NB = (NN + 255) / 256;  // 196

    cudaMemsetAsync(counts, 0, NN * sizeof(int));
    cudaMemsetAsync(tiles, 0, 256 * sizeof(ull));
    wsplit_kernel<<<128, 256>>>(W0, W1);                       // k1
    count_kernel<<<(etot + 511) / 512, 512>>>(ei, E, etot);    // k2
    scan_kernel<<<NB, 256>>>(etot);                            // k3

    const int smem_mma3 = 107520;
    const int smem_mma2 = 107520 - 64 * 136 * 2;               // 90112
    const int smem_lin40 = (128 * 40 + 128 * 66 + 128) * 4;    // 54784
    cudaFuncSetAttribute(lin128_mma3_kernel, cudaFuncAttributeMaxDynamicSharedMemorySize, smem_mma3);
    cudaFuncSetAttribute(lin128_mma2_kernel, cudaFuncAttributeMaxDynamicSharedMemorySize, smem_mma2);
    cudaFuncSetAttribute(lin40_kernel, cudaFuncAttributeMaxDynamicSharedMemorySize, smem_lin40);

    int lin_grid = (NN + 63) / 64;            // 782
    int agg_grid = (NN * 32 + 255) / 256;     // warp per node

    // layer 0 GEMM before fill (independent of CSR); k4 = ncu capture target
    lin128_mma3_kernel<<<lin_grid, 256, smem_mma3>>>(x, Wh, Wl, as0, ad0, H16, asrc, adst, NN);
    fill_kernel<<<(etot + 511) / 512, 512>>>(ei, E, etot);     // k5
    agg_kernel<<<agg_grid, 256>>>(H16, asrc, adst, b0, A16);
    // layer 1 (fp16 input, 2-term)
    lin128_mma2_kernel<<<lin_grid, 256, smem_mma2>>>(A16, Wh + 16384, Wl + 16384, as1, ad1, H16, asrc, adst, NN);
    agg_kernel<<<agg_grid, 256>>>(H16, asrc, adst, b1, A16);
    // layer 2
    lin40_kernel<<<lin_grid, 320, smem_lin40>>>(A16, W2, as2, ad2, H16, asrc, adst, NN);
    agg2_kernel<<<agg_grid, 256>>>(H16, asrc, adst, b2, out);

    (void)n_in; (void)out_size;
}